// round 1
// baseline (speedup 1.0000x reference)
#include <cuda_runtime.h>
#include <cuda_bf16.h>

#define NN   50000
#define NE   800000
#define ENT  (NE + NN)        // edges + self loops
#define FIN  128
#define FOUT 64
#define SLOPE 0.2f

// ---------------- scratch (no allocations allowed -> __device__ globals) ----
__device__ float    g_h[(size_t)NN * FOUT];   // x @ W
__device__ float    g_asrc[NN];               // h . att_src
__device__ float    g_adst[NN];               // h . att_dst
__device__ unsigned g_menc[NN];               // order-encoded segment max
__device__ float    g_denom[NN];              // softmax denominator
__device__ float    g_e[ENT];                 // per-edge logit, then exp

// order-preserving float<->uint encoding for atomicMax on floats
__device__ __forceinline__ unsigned f2u_ord(float f) {
    unsigned u = __float_as_uint(f);
    return (u & 0x80000000u) ? ~u : (u | 0x80000000u);
}
__device__ __forceinline__ float u2f_ord(unsigned u) {
    return (u & 0x80000000u) ? __uint_as_float(u & 0x7fffffffu)
                             : __uint_as_float(~u);
}

__device__ __forceinline__ float leaky(float v) {
    return v > 0.f ? v : SLOPE * v;
}

// ---------------------------------------------------------------------------
// K1: h = x @ W  (one row per warp), fused epilogue:
//   a_src[row], a_dst[row], self-loop logit -> g_e[NE+row],
//   g_menc init with self-loop logit, g_denom init 0, out[row] = bias
// ---------------------------------------------------------------------------
__global__ __launch_bounds__(256) void k_gemm(
    const float* __restrict__ x, const float* __restrict__ W,
    const float* __restrict__ att_src, const float* __restrict__ att_dst,
    const float* __restrict__ bias, float* __restrict__ out)
{
    __shared__ float2 Wsh[FIN * 32];   // Wsh[k*32+l] = (W[k][2l], W[k][2l+1])
    __shared__ float  xs[8][FIN];

    int tid = threadIdx.x;
    for (int idx = tid; idx < FIN * 32; idx += 256) {
        int k = idx >> 5, l = idx & 31;
        Wsh[idx] = make_float2(W[k * FOUT + 2 * l], W[k * FOUT + 2 * l + 1]);
    }
    __syncthreads();

    int lane = tid & 31, w = tid >> 5;
    float2 as2 = ((const float2*)att_src)[lane];
    float2 ad2 = ((const float2*)att_dst)[lane];
    float2 bv  = ((const float2*)bias)[lane];

    int stride = gridDim.x * 8;
    for (int row = blockIdx.x * 8 + w; row < NN; row += stride) {
        float4 xv = ((const float4*)(x + (size_t)row * FIN))[lane];
        ((float4*)xs[w])[lane] = xv;
        __syncwarp();

        float a0 = 0.f, a1 = 0.f;
        #pragma unroll
        for (int k0 = 0; k0 < FIN; k0 += 4) {
            float4 xk = *((const float4*)&xs[w][k0]);
            float2 w0 = Wsh[(k0 + 0) * 32 + lane];
            float2 w1 = Wsh[(k0 + 1) * 32 + lane];
            float2 w2 = Wsh[(k0 + 2) * 32 + lane];
            float2 w3 = Wsh[(k0 + 3) * 32 + lane];
            a0 += xk.x * w0.x; a1 += xk.x * w0.y;
            a0 += xk.y * w1.x; a1 += xk.y * w1.y;
            a0 += xk.z * w2.x; a1 += xk.z * w2.y;
            a0 += xk.w * w3.x; a1 += xk.w * w3.y;
        }
        __syncwarp();   // protect xs before next iteration's overwrite

        ((float2*)(g_h + (size_t)row * FOUT))[lane] = make_float2(a0, a1);
        ((float2*)(out + (size_t)row * FOUT))[lane] = bv;   // out = bias init

        float ps = a0 * as2.x + a1 * as2.y;
        float pd = a0 * ad2.x + a1 * ad2.y;
        #pragma unroll
        for (int off = 16; off; off >>= 1) {
            ps += __shfl_xor_sync(0xffffffffu, ps, off);
            pd += __shfl_xor_sync(0xffffffffu, pd, off);
        }
        if (lane == 0) {
            g_asrc[row] = ps;
            g_adst[row] = pd;
            float se = leaky(ps + pd);        // self-loop logit
            g_e[NE + row] = se;
            g_menc[row]   = f2u_ord(se);      // max init includes self loop
            g_denom[row]  = 0.f;
        }
    }
}

// ---------------------------------------------------------------------------
// K2: per-edge logit + scatter max
// ---------------------------------------------------------------------------
__global__ __launch_bounds__(256) void k_edge_max(const int* __restrict__ ei)
{
    int i = blockIdx.x * blockDim.x + threadIdx.x;
    if (i >= NE) return;
    int s = ei[i], d = ei[NE + i];
    float e = leaky(g_asrc[s] + g_adst[d]);
    g_e[i] = e;
    atomicMax(&g_menc[d], f2u_ord(e));
}

// ---------------------------------------------------------------------------
// K3: exp(e - max) + scatter denom sum (includes self loops)
// ---------------------------------------------------------------------------
__global__ __launch_bounds__(256) void k_edge_exp(const int* __restrict__ ei)
{
    int i = blockIdx.x * blockDim.x + threadIdx.x;
    if (i >= ENT) return;
    int d = (i < NE) ? ei[NE + i] : (i - NE);
    float m  = u2f_ord(g_menc[d]);
    float ex = __expf(g_e[i] - m);
    g_e[i] = ex;
    atomicAdd(&g_denom[d], ex);
}

// ---------------------------------------------------------------------------
// K4: out[dst] += (ex/denom[dst]) * h[src]   (16 float4 chunks per edge)
// ---------------------------------------------------------------------------
__global__ __launch_bounds__(256) void k_aggregate(const int* __restrict__ ei,
                                                   float* __restrict__ out)
{
    long long t = (long long)blockIdx.x * blockDim.x + threadIdx.x;
    if (t >= (long long)ENT * 16) return;
    int e = (int)(t >> 4);
    int c = (int)(t & 15);
    int s, d;
    if (e < NE) { s = ei[e]; d = ei[NE + e]; }
    else        { s = d = e - NE; }
    float alpha = g_e[e] / g_denom[d];
    float4 hv = ((const float4*)(g_h + (size_t)s * FOUT))[c];
    float4 v  = make_float4(alpha * hv.x, alpha * hv.y,
                            alpha * hv.z, alpha * hv.w);
    atomicAdd(((float4*)(out + (size_t)d * FOUT)) + c, v);
}

// ---------------------------------------------------------------------------
extern "C" void kernel_launch(void* const* d_in, const int* in_sizes, int n_in,
                              void* d_out, int out_size)
{
    const float* x    = (const float*)d_in[0];
    const int*   ei   = (const int*)  d_in[1];   // [2, NE]: row0=src, row1=dst
    const float* W    = (const float*)d_in[2];
    const float* asrc = (const float*)d_in[3];
    const float* adst = (const float*)d_in[4];
    const float* bias = (const float*)d_in[5];
    float* out = (float*)d_out;

    k_gemm<<<888, 256>>>(x, W, asrc, adst, bias, out);
    k_edge_max<<<(NE + 255) / 256, 256>>>(ei);
    k_edge_exp<<<(ENT + 255) / 256, 256>>>(ei);
    long long tot = (long long)ENT * 16;
    k_aggregate<<<(int)((tot + 255) / 256), 256>>>(ei, out);
}